// round 13
// baseline (speedup 1.0000x reference)
#include <cuda_runtime.h>
#include <cuda_fp16.h>
#include <cstdint>

// ============================================================================
// SparseUncompressConvolution via mma.sync fp16 (m16n8k16, fp32 accumulate).
//   even w=2j   : lq + relu(W1*U[j] + b) + U[j]/3
//   odd  w=2j+1 : lq + relu(W0*U[j] + W2*U[j+1] + b) + (U[j]+U[j+1])/3
// Acc_even = A*W1^T ; Acc_odd = A*W0^T + A_shift*W2^T (A_shift = A rows +1)
// R12: 128 threads / 4 warps per CTA, warp tile 32x64 (acc 128 regs, budget
//      255 via launch_bounds(128,2)). 20% fewer ldsm per HMMA, 2x per-warp
//      ILP, still 2 CTAs/SM for epilogue overlap. mbarrier pipeline from R11.
// ============================================================================

#define BM 128
#define BN 64
#define BK 64                  // fp16 elems per chunk row = 128 bytes
#define NCHUNK 8               // 512 / BK
#define NTHREADS 128
#define ROWSTRIDE 144          // 128B data + 16B pad (conflict-free ldmatrix)
#define A_BYTES (129 * ROWSTRIDE)
#define B_BAND_BYTES (64 * ROWSTRIDE)
#define STAGE (A_BYTES + 3 * B_BAND_BYTES)     // 46224
#define MBAR_BYTES 64
#define SMEM_BYTES (MBAR_BYTES + 2 * STAGE)
#define OFF_FULL(s)  ((s) * 8)
#define OFF_EMPTY(s) (16 + (s) * 8)
#define A_CNT 1032             // 129 rows * 8 x16B chunks
#define TOT_CNT (A_CNT + 1536) // + 3*64*8

#define NU8 (32768 * 512 / 8)
#define NW8 (512 * 1536 / 8)

__device__ __half g_Uh[32768 * 512];
__device__ __half g_Wh[512 * 1536];

__device__ __forceinline__ uint32_t s2u(const void* p) {
    uint32_t a;
    asm("{ .reg .u64 t; cvta.to.shared.u64 t, %1; cvt.u32.u64 %0, t; }" : "=r"(a) : "l"(p));
    return a;
}
__device__ __forceinline__ void cp16(uint32_t dst, const void* src) {
    asm volatile("cp.async.cg.shared.global [%0], [%1], 16;" :: "r"(dst), "l"(src));
}
__device__ __forceinline__ void ldsm4(uint32_t addr, uint32_t* r) {
    asm volatile("ldmatrix.sync.aligned.m8n8.x4.shared.b16 {%0,%1,%2,%3}, [%4];"
                 : "=r"(r[0]), "=r"(r[1]), "=r"(r[2]), "=r"(r[3]) : "r"(addr));
}
__device__ __forceinline__ void mma16(float* d, const uint32_t* a, uint32_t b0, uint32_t b1) {
    asm volatile(
        "mma.sync.aligned.m16n8k16.row.col.f32.f16.f16.f32 "
        "{%0,%1,%2,%3}, {%4,%5,%6,%7}, {%8,%9}, {%0,%1,%2,%3};"
        : "+f"(d[0]), "+f"(d[1]), "+f"(d[2]), "+f"(d[3])
        : "r"(a[0]), "r"(a[1]), "r"(a[2]), "r"(a[3]), "r"(b0), "r"(b1));
}

#define MBAR_INIT(a, c) \
    asm volatile("mbarrier.init.shared.b64 [%0], %1;" :: "r"(a), "r"(c) : "memory")
#define MBAR_ARRIVE(a) \
    asm volatile("mbarrier.arrive.shared.b64 _, [%0];" :: "r"(a) : "memory")
#define CPASYNC_MBAR_ARRIVE(a) \
    asm volatile("cp.async.mbarrier.arrive.noinc.shared.b64 [%0];" :: "r"(a) : "memory")
#define MBAR_WAIT(a, ph) do {                                                 \
    asm volatile(                                                             \
        "{\n\t.reg .pred P1;\n\t"                                             \
        "WAIT_LOOP_%=:\n\t"                                                   \
        "mbarrier.try_wait.parity.acquire.cta.shared::cta.b64 P1, [%0], %1, 0x989680;\n\t" \
        "@P1 bra.uni WAIT_DONE_%=;\n\t"                                       \
        "bra.uni WAIT_LOOP_%=;\n\t"                                           \
        "WAIT_DONE_%=:\n\t}"                                                  \
        :: "r"(a), "r"(ph) : "memory");                                       \
} while (0)

// ---------------------------------------------------------------------------
__global__ void __launch_bounds__(256) f2h_fused(const float* __restrict__ U,
                                                 const float* __restrict__ W) {
    int idx = blockIdx.x * blockDim.x + threadIdx.x;
    const float4* src;
    uint4* dst;
    if (idx < NU8) {
        src = (const float4*)U + idx * 2;
        dst = (uint4*)g_Uh + idx;
    } else {
        int j = idx - NU8;
        if (j >= NW8) return;
        src = (const float4*)W + j * 2;
        dst = (uint4*)g_Wh + j;
    }
    float4 v0 = src[0], v1 = src[1];
    __half2 h0 = __floats2half2_rn(v0.x, v0.y);
    __half2 h1 = __floats2half2_rn(v0.z, v0.w);
    __half2 h2 = __floats2half2_rn(v1.x, v1.y);
    __half2 h3 = __floats2half2_rn(v1.z, v1.w);
    uint4 pk;
    pk.x = *(uint32_t*)&h0; pk.y = *(uint32_t*)&h1;
    pk.z = *(uint32_t*)&h2; pk.w = *(uint32_t*)&h3;
    *dst = pk;
}

// ---------------------------------------------------------------------------
__global__ void __launch_bounds__(NTHREADS, 2)
suc_mma_kernel(const float* __restrict__ lq,
               const float* __restrict__ bias, float* __restrict__ out)
{
    extern __shared__ __align__(16) char smem[];
    const uint32_t sb = s2u(smem);
    char* stage_base = smem + MBAR_BYTES;
    const int tid = threadIdx.x;
    const int lane = tid & 31;
    const int wm = tid >> 5;         // warp = m-block (32 rows); warp covers all 64 n
    const int n0 = blockIdx.x * BN;
    const int r0 = blockIdx.y * BM;
    const bool zb = (((r0 + BM) & 1023) == 0);

    if (tid == 0) {
        MBAR_INIT(sb + OFF_FULL(0), NTHREADS);
        MBAR_INIT(sb + OFF_FULL(1), NTHREADS);
        MBAR_INIT(sb + OFF_EMPTY(0), NTHREADS);
        MBAR_INIT(sb + OFF_EMPTY(1), NTHREADS);
    }
    if (zb && tid < 64) {
        int s = tid >> 5, w = tid & 31;
        ((uint32_t*)(stage_base + s * STAGE + 128 * ROWSTRIDE))[w] = 0u;
    }
    __syncthreads();

    const uint32_t stg = sb + MBAR_BYTES;

    auto issue_load = [&](int c, int s) {
        const int kt = c * BK;
        const uint32_t stb = stg + s * STAGE;
        #pragma unroll 1
        for (int i = tid; i < TOT_CNT; i += NTHREADS) {
            if (i < A_CNT) {
                int r = i >> 3, cc = i & 7;
                if (!(zb && r == 128))
                    cp16(stb + r * ROWSTRIDE + cc * 16,
                         &g_Uh[(r0 + r) * 512 + kt + cc * 8]);
            } else {
                int b = i - A_CNT;
                int band = b >> 9, rem = b & 511, n = rem >> 3, cc = rem & 7;
                cp16(stb + A_BYTES + band * B_BAND_BYTES + n * ROWSTRIDE + cc * 16,
                     &g_Wh[(n0 + n) * 1536 + band * 512 + kt + cc * 8]);
            }
        }
        CPASYNC_MBAR_ARRIVE(sb + OFF_FULL(s));
    };

    uint32_t aoff[2];
    #pragma unroll
    for (int mt = 0; mt < 2; mt++)
        aoff[mt] = (wm * 32 + mt * 16 + (lane & 15)) * ROWSTRIDE + (lane >> 4) * 16;
    // B fragments: p in 0..3 covers n16 groups of the full 64-col band
    uint32_t boff[3][4];
    #pragma unroll
    for (int band = 0; band < 3; band++)
        #pragma unroll
        for (int p = 0; p < 4; p++)
            boff[band][p] = A_BYTES + band * B_BAND_BYTES
                + (p * 16 + (lane & 7) + ((lane >> 4) & 1) * 8) * ROWSTRIDE
                + ((lane >> 3) & 1) * 16;

    float ae[2][8][4] = {};
    float ao[2][8][4] = {};

    issue_load(0, 0);
    issue_load(1, 1);

    #pragma unroll 1
    for (int c = 0; c < NCHUNK; ++c) {
        const int s = c & 1;
        const uint32_t ph = (c >> 1) & 1;
        MBAR_WAIT(sb + OFF_FULL(s), ph);

        const uint32_t stb = stg + s * STAGE;
        #pragma unroll
        for (int g = 0; g < 4; g++) {
            const uint32_t ko = g * 32;
            uint32_t a[2][4], as[2][4];
            #pragma unroll
            for (int mt = 0; mt < 2; mt++) {
                ldsm4(stb + aoff[mt] + ko, a[mt]);
                ldsm4(stb + aoff[mt] + ROWSTRIDE + ko, as[mt]);   // +1 row shift
            }
            {   // band 1 -> even acc
                uint32_t b[4][4];
                #pragma unroll
                for (int p = 0; p < 4; p++) ldsm4(stb + boff[1][p] + ko, b[p]);
                #pragma unroll
                for (int mt = 0; mt < 2; mt++)
                    #pragma unroll
                    for (int nt = 0; nt < 8; nt++)
                        mma16(ae[mt][nt], a[mt], b[nt >> 1][(nt & 1) * 2],
                              b[nt >> 1][(nt & 1) * 2 + 1]);
            }
            {   // band 0 -> odd acc (A)
                uint32_t b[4][4];
                #pragma unroll
                for (int p = 0; p < 4; p++) ldsm4(stb + boff[0][p] + ko, b[p]);
                #pragma unroll
                for (int mt = 0; mt < 2; mt++)
                    #pragma unroll
                    for (int nt = 0; nt < 8; nt++)
                        mma16(ao[mt][nt], a[mt], b[nt >> 1][(nt & 1) * 2],
                              b[nt >> 1][(nt & 1) * 2 + 1]);
            }
            {   // band 2 -> odd acc (A shifted)
                uint32_t b[4][4];
                #pragma unroll
                for (int p = 0; p < 4; p++) ldsm4(stb + boff[2][p] + ko, b[p]);
                #pragma unroll
                for (int mt = 0; mt < 2; mt++)
                    #pragma unroll
                    for (int nt = 0; nt < 8; nt++)
                        mma16(ao[mt][nt], as[mt], b[nt >> 1][(nt & 1) * 2],
                              b[nt >> 1][(nt & 1) * 2 + 1]);
            }
        }
        MBAR_ARRIVE(sb + OFF_EMPTY(s));
        if (c + 2 < NCHUNK) {
            MBAR_WAIT(sb + OFF_EMPTY(s), ph);
            issue_load(c + 2, s);
        }
    }

    // ---- fused epilogue: bias + relu + residual + res_connect ----
    const int l4 = lane >> 2;
    const int l2 = (lane & 3) * 2;
    #pragma unroll
    for (int mt = 0; mt < 2; mt++) {
        #pragma unroll
        for (int h = 0; h < 2; h++) {
            const int rg = r0 + wm * 32 + mt * 16 + h * 8 + l4;
            const int j = rg & 1023;
            const int bh = rg >> 10;
            const bool v1 = (j != 1023);
            const int ie_base = (bh * 2048 + 2 * j) * 512;
            #pragma unroll
            for (int nt = 0; nt < 8; nt++) {
                const int dof = n0 + nt * 8 + l2;
                const float2 u0 = __half22float2(*(const __half2*)&g_Uh[rg * 512 + dof]);
                float2 u1 = make_float2(0.f, 0.f);
                if (v1) u1 = __half22float2(*(const __half2*)&g_Uh[(rg + 1) * 512 + dof]);
                const float2 bv = *(const float2*)&bias[dof];
                const int ie = ie_base + dof;
                const int io = ie + 512;
                const float2 lqe = *(const float2*)&lq[ie];
                const float2 lqo = *(const float2*)&lq[io];
                const float e0 = ae[mt][nt][h * 2 + 0], e1 = ae[mt][nt][h * 2 + 1];
                const float o0 = ao[mt][nt][h * 2 + 0], o1 = ao[mt][nt][h * 2 + 1];
                float2 re, ro;
                re.x = lqe.x + fmaxf(e0 + bv.x, 0.f) + u0.x * (1.f / 3.f);
                re.y = lqe.y + fmaxf(e1 + bv.y, 0.f) + u0.y * (1.f / 3.f);
                ro.x = lqo.x + fmaxf(o0 + bv.x, 0.f) + (u0.x + u1.x) * (1.f / 3.f);
                ro.y = lqo.y + fmaxf(o1 + bv.y, 0.f) + (u0.y + u1.y) * (1.f / 3.f);
                *(float2*)&out[ie] = re;
                *(float2*)&out[io] = ro;
            }
        }
    }
}

// ============================================================================
extern "C" void kernel_launch(void* const* d_in, const int* in_sizes, int n_in,
                              void* d_out, int out_size)
{
    const float* lq   = (const float*)d_in[0];
    const float* U    = (const float*)d_in[1];
    const float* W    = (const float*)d_in[2];
    const float* bias = (const float*)d_in[3];

    f2h_fused<<<(NU8 + NW8 + 255) / 256, 256>>>(U, W);

    cudaFuncSetAttribute(suc_mma_kernel, cudaFuncAttributeMaxDynamicSharedMemorySize,
                         SMEM_BYTES);
    dim3 grid(512 / BN, 32768 / BM);  // (8, 256)
    suc_mma_kernel<<<grid, NTHREADS, SMEM_BYTES>>>(lq, bias, (float*)d_out);
}

// round 14
// speedup vs baseline: 1.2084x; 1.2084x over previous
#include <cuda_runtime.h>
#include <cuda_fp16.h>
#include <cstdint>

// ============================================================================
// SparseUncompressConvolution via mma.sync fp16 (m16n8k16, fp32 accumulate).
//   even w=2j   : lq + relu(W1*U[j] + b) + U[j]/3
//   odd  w=2j+1 : lq + relu(W0*U[j] + W2*U[j+1] + b) + (U[j]+U[j+1])/3
// Acc_even = A*W1^T ; Acc_odd = A*W0^T + A_shift*W2^T (A_shift = A rows +1)
// R14: R11 config (best: 182.6us main) + cache-policy hints:
//      lq via ld.global.cs, out via st.global.cs (read/write-once streams,
//      evict-first -> protect L2 residency of U/W operands), __ldg epilogue.
// ============================================================================

#define BM 128
#define BN 64
#define BK 64                  // fp16 elems per chunk row = 128 bytes
#define NCHUNK 8               // 512 / BK
#define ROWSTRIDE 144          // 128B data + 16B pad (conflict-free ldmatrix)
#define A_BYTES (129 * ROWSTRIDE)
#define B_BAND_BYTES (64 * ROWSTRIDE)
#define STAGE (A_BYTES + 3 * B_BAND_BYTES)     // 46224
#define MBAR_BYTES 64
#define SMEM_BYTES (MBAR_BYTES + 2 * STAGE)
#define OFF_FULL(s)  ((s) * 8)
#define OFF_EMPTY(s) (16 + (s) * 8)
#define A_CNT 1032             // 129 rows * 8 x16B chunks
#define TOT_CNT (A_CNT + 1536) // + 3*64*8

#define NU8 (32768 * 512 / 8)
#define NW8 (512 * 1536 / 8)

__device__ __half g_Uh[32768 * 512];
__device__ __half g_Wh[512 * 1536];

__device__ __forceinline__ uint32_t s2u(const void* p) {
    uint32_t a;
    asm("{ .reg .u64 t; cvta.to.shared.u64 t, %1; cvt.u32.u64 %0, t; }" : "=r"(a) : "l"(p));
    return a;
}
__device__ __forceinline__ void cp16(uint32_t dst, const void* src) {
    asm volatile("cp.async.cg.shared.global [%0], [%1], 16;" :: "r"(dst), "l"(src));
}
__device__ __forceinline__ void ldsm4(uint32_t addr, uint32_t* r) {
    asm volatile("ldmatrix.sync.aligned.m8n8.x4.shared.b16 {%0,%1,%2,%3}, [%4];"
                 : "=r"(r[0]), "=r"(r[1]), "=r"(r[2]), "=r"(r[3]) : "r"(addr));
}
__device__ __forceinline__ void mma16(float* d, const uint32_t* a, uint32_t b0, uint32_t b1) {
    asm volatile(
        "mma.sync.aligned.m16n8k16.row.col.f32.f16.f16.f32 "
        "{%0,%1,%2,%3}, {%4,%5,%6,%7}, {%8,%9}, {%0,%1,%2,%3};"
        : "+f"(d[0]), "+f"(d[1]), "+f"(d[2]), "+f"(d[3])
        : "r"(a[0]), "r"(a[1]), "r"(a[2]), "r"(a[3]), "r"(b0), "r"(b1));
}
__device__ __forceinline__ float2 ldg_cs_f2(const float* p) {
    float2 v;
    asm volatile("ld.global.cs.v2.f32 {%0,%1}, [%2];" : "=f"(v.x), "=f"(v.y) : "l"(p));
    return v;
}
__device__ __forceinline__ void stg_cs_f2(float* p, float2 v) {
    asm volatile("st.global.cs.v2.f32 [%0], {%1,%2};" :: "l"(p), "f"(v.x), "f"(v.y));
}

#define MBAR_INIT(a, c) \
    asm volatile("mbarrier.init.shared.b64 [%0], %1;" :: "r"(a), "r"(c) : "memory")
#define MBAR_ARRIVE(a) \
    asm volatile("mbarrier.arrive.shared.b64 _, [%0];" :: "r"(a) : "memory")
#define CPASYNC_MBAR_ARRIVE(a) \
    asm volatile("cp.async.mbarrier.arrive.noinc.shared.b64 [%0];" :: "r"(a) : "memory")
#define MBAR_WAIT(a, ph) do {                                                 \
    asm volatile(                                                             \
        "{\n\t.reg .pred P1;\n\t"                                             \
        "WAIT_LOOP_%=:\n\t"                                                   \
        "mbarrier.try_wait.parity.acquire.cta.shared::cta.b64 P1, [%0], %1, 0x989680;\n\t" \
        "@P1 bra.uni WAIT_DONE_%=;\n\t"                                       \
        "bra.uni WAIT_LOOP_%=;\n\t"                                           \
        "WAIT_DONE_%=:\n\t}"                                                  \
        :: "r"(a), "r"(ph) : "memory");                                       \
} while (0)

// ---------------------------------------------------------------------------
__global__ void __launch_bounds__(256) f2h_fused(const float* __restrict__ U,
                                                 const float* __restrict__ W) {
    int idx = blockIdx.x * blockDim.x + threadIdx.x;
    const float4* src;
    uint4* dst;
    if (idx < NU8) {
        src = (const float4*)U + idx * 2;
        dst = (uint4*)g_Uh + idx;
    } else {
        int j = idx - NU8;
        if (j >= NW8) return;
        src = (const float4*)W + j * 2;
        dst = (uint4*)g_Wh + j;
    }
    float4 v0 = src[0], v1 = src[1];
    __half2 h0 = __floats2half2_rn(v0.x, v0.y);
    __half2 h1 = __floats2half2_rn(v0.z, v0.w);
    __half2 h2 = __floats2half2_rn(v1.x, v1.y);
    __half2 h3 = __floats2half2_rn(v1.z, v1.w);
    uint4 pk;
    pk.x = *(uint32_t*)&h0; pk.y = *(uint32_t*)&h1;
    pk.z = *(uint32_t*)&h2; pk.w = *(uint32_t*)&h3;
    *dst = pk;
}

// ---------------------------------------------------------------------------
__global__ void __launch_bounds__(256, 2)
suc_mma_kernel(const float* __restrict__ lq,
               const float* __restrict__ bias, float* __restrict__ out)
{
    extern __shared__ __align__(16) char smem[];
    const uint32_t sb = s2u(smem);
    char* stage_base = smem + MBAR_BYTES;
    const int tid = threadIdx.x;
    const int lane = tid & 31;
    const int wid = tid >> 5;
    const int wm = wid & 3;
    const int wn = wid >> 2;
    const int n0 = blockIdx.x * BN;
    const int r0 = blockIdx.y * BM;
    const bool zb = (((r0 + BM) & 1023) == 0);

    if (tid == 0) {
        MBAR_INIT(sb + OFF_FULL(0), 256);
        MBAR_INIT(sb + OFF_FULL(1), 256);
        MBAR_INIT(sb + OFF_EMPTY(0), 256);
        MBAR_INIT(sb + OFF_EMPTY(1), 256);
    }
    if (zb && tid < 64) {
        int s = tid >> 5, w = tid & 31;
        ((uint32_t*)(stage_base + s * STAGE + 128 * ROWSTRIDE))[w] = 0u;
    }
    __syncthreads();   // one-time: mbarrier init + zeroing visible

    const uint32_t stg = sb + MBAR_BYTES;

    auto issue_load = [&](int c, int s) {
        const int kt = c * BK;
        const uint32_t stb = stg + s * STAGE;
        #pragma unroll 1
        for (int i = tid; i < TOT_CNT; i += 256) {
            if (i < A_CNT) {
                int r = i >> 3, cc = i & 7;
                if (!(zb && r == 128))
                    cp16(stb + r * ROWSTRIDE + cc * 16,
                         &g_Uh[(r0 + r) * 512 + kt + cc * 8]);
            } else {
                int b = i - A_CNT;
                int band = b >> 9, rem = b & 511, n = rem >> 3, cc = rem & 7;
                cp16(stb + A_BYTES + band * B_BAND_BYTES + n * ROWSTRIDE + cc * 16,
                     &g_Wh[(n0 + n) * 1536 + band * 512 + kt + cc * 8]);
            }
        }
        CPASYNC_MBAR_ARRIVE(sb + OFF_FULL(s));
    };

    uint32_t aoff[2];
    #pragma unroll
    for (int mt = 0; mt < 2; mt++)
        aoff[mt] = (wm * 32 + mt * 16 + (lane & 15)) * ROWSTRIDE + (lane >> 4) * 16;
    uint32_t boff[3][2];
    #pragma unroll
    for (int band = 0; band < 3; band++)
        #pragma unroll
        for (int p = 0; p < 2; p++)
            boff[band][p] = A_BYTES + band * B_BAND_BYTES
                + (wn * 32 + p * 16 + (lane & 7) + ((lane >> 4) & 1) * 8) * ROWSTRIDE
                + ((lane >> 3) & 1) * 16;

    float ae[2][4][4] = {};
    float ao[2][4][4] = {};

    issue_load(0, 0);
    issue_load(1, 1);

    #pragma unroll 1
    for (int c = 0; c < NCHUNK; ++c) {
        const int s = c & 1;
        const uint32_t ph = (c >> 1) & 1;
        MBAR_WAIT(sb + OFF_FULL(s), ph);

        const uint32_t stb = stg + s * STAGE;
        #pragma unroll
        for (int g = 0; g < 4; g++) {
            const uint32_t ko = g * 32;
            uint32_t a[2][4], as[2][4];
            #pragma unroll
            for (int mt = 0; mt < 2; mt++) {
                ldsm4(stb + aoff[mt] + ko, a[mt]);
                ldsm4(stb + aoff[mt] + ROWSTRIDE + ko, as[mt]);   // +1 row shift
            }
            uint32_t b1[2][4], b0[2][4], b2[2][4];
            ldsm4(stb + boff[1][0] + ko, b1[0]);
            ldsm4(stb + boff[1][1] + ko, b1[1]);
            ldsm4(stb + boff[0][0] + ko, b0[0]);
            ldsm4(stb + boff[0][1] + ko, b0[1]);
            ldsm4(stb + boff[2][0] + ko, b2[0]);
            ldsm4(stb + boff[2][1] + ko, b2[1]);
            #pragma unroll
            for (int mt = 0; mt < 2; mt++)
                #pragma unroll
                for (int nt = 0; nt < 4; nt++) {
                    const int hp = nt >> 1, hq = (nt & 1) * 2;
                    mma16(ae[mt][nt], a[mt], b1[hp][hq], b1[hp][hq + 1]);
                    mma16(ao[mt][nt], a[mt], b0[hp][hq], b0[hp][hq + 1]);
                }
            #pragma unroll
            for (int mt = 0; mt < 2; mt++)
                #pragma unroll
                for (int nt = 0; nt < 4; nt++) {
                    const int hp = nt >> 1, hq = (nt & 1) * 2;
                    mma16(ao[mt][nt], as[mt], b2[hp][hq], b2[hp][hq + 1]);
                }
        }
        MBAR_ARRIVE(sb + OFF_EMPTY(s));
        if (c + 2 < NCHUNK) {
            MBAR_WAIT(sb + OFF_EMPTY(s), ph);
            issue_load(c + 2, s);
        }
    }

    // ---- fused epilogue: bias + relu + residual + res_connect ----
    // lq: evict-first (read once); out: evict-first (write once);
    // g_Uh/bias: read-only path (L2-resident).
    const int l4 = lane >> 2;
    const int l2 = (lane & 3) * 2;
    #pragma unroll
    for (int mt = 0; mt < 2; mt++) {
        #pragma unroll
        for (int h = 0; h < 2; h++) {
            const int rg = r0 + wm * 32 + mt * 16 + h * 8 + l4;
            const int j = rg & 1023;
            const int bh = rg >> 10;
            const bool v1 = (j != 1023);
            const int ie_base = (bh * 2048 + 2 * j) * 512;
            #pragma unroll
            for (int nt = 0; nt < 4; nt++) {
                const int dof = n0 + wn * 32 + nt * 8 + l2;
                const __half2 u0h = __ldg((const __half2*)&g_Uh[rg * 512 + dof]);
                const float2 u0 = __half22float2(u0h);
                float2 u1 = make_float2(0.f, 0.f);
                if (v1) u1 = __half22float2(__ldg((const __half2*)&g_Uh[(rg + 1) * 512 + dof]));
                const float2 bv = *(const float2*)&bias[dof];
                const int ie = ie_base + dof;
                const int io = ie + 512;
                const float2 lqe = ldg_cs_f2(&lq[ie]);
                const float2 lqo = ldg_cs_f2(&lq[io]);
                const float e0 = ae[mt][nt][h * 2 + 0], e1 = ae[mt][nt][h * 2 + 1];
                const float o0 = ao[mt][nt][h * 2 + 0], o1 = ao[mt][nt][h * 2 + 1];
                float2 re, ro;
                re.x = lqe.x + fmaxf(e0 + bv.x, 0.f) + u0.x * (1.f / 3.f);
                re.y = lqe.y + fmaxf(e1 + bv.y, 0.f) + u0.y * (1.f / 3.f);
                ro.x = lqo.x + fmaxf(o0 + bv.x, 0.f) + (u0.x + u1.x) * (1.f / 3.f);
                ro.y = lqo.y + fmaxf(o1 + bv.y, 0.f) + (u0.y + u1.y) * (1.f / 3.f);
                stg_cs_f2(&out[ie], re);
                stg_cs_f2(&out[io], ro);
            }
        }
    }
}

// ============================================================================
extern "C" void kernel_launch(void* const* d_in, const int* in_sizes, int n_in,
                              void* d_out, int out_size)
{
    const float* lq   = (const float*)d_in[0];
    const float* U    = (const float*)d_in[1];
    const float* W    = (const float*)d_in[2];
    const float* bias = (const float*)d_in[3];

    f2h_fused<<<(NU8 + NW8 + 255) / 256, 256>>>(U, W);

    cudaFuncSetAttribute(suc_mma_kernel, cudaFuncAttributeMaxDynamicSharedMemorySize,
                         SMEM_BYTES);
    dim3 grid(512 / BN, 32768 / BM);  // (8, 256)
    suc_mma_kernel<<<grid, 256, SMEM_BYTES>>>(lq, bias, (float*)d_out);
}

// round 15
// speedup vs baseline: 1.2609x; 1.0434x over previous
#include <cuda_runtime.h>
#include <cuda_fp16.h>
#include <cstdint>

// ============================================================================
// SparseUncompressConvolution via mma.sync fp16 (m16n8k16, fp32 accumulate).
//   even w=2j   : lq + relu(W1*U[j] + b) + U[j]/3
//   odd  w=2j+1 : lq + relu(W0*U[j] + W2*U[j+1] + b) + (U[j]+U[j+1])/3
// Acc_even = A*W1^T ; Acc_odd = A*W0^T + A_shift*W2^T (A_shift = A rows +1)
// R15: main kernel = exact R11 (best measured: 182.6us). Prepass rewritten
//      for MLP=8 (4 independent 16B ld/st per thread) -> ~55% -> ~80% DRAM.
// ============================================================================

#define BM 128
#define BN 64
#define BK 64                  // fp16 elems per chunk row = 128 bytes
#define NCHUNK 8               // 512 / BK
#define ROWSTRIDE 144          // 128B data + 16B pad (conflict-free ldmatrix)
#define A_BYTES (129 * ROWSTRIDE)
#define B_BAND_BYTES (64 * ROWSTRIDE)
#define STAGE (A_BYTES + 3 * B_BAND_BYTES)     // 46224
#define MBAR_BYTES 64
#define SMEM_BYTES (MBAR_BYTES + 2 * STAGE)
#define OFF_FULL(s)  ((s) * 8)
#define OFF_EMPTY(s) (16 + (s) * 8)
#define A_CNT 1032             // 129 rows * 8 x16B chunks
#define TOT_CNT (A_CNT + 1536) // + 3*64*8

#define NU8 (32768 * 512 / 8)  // 2097152 uint4 outputs for U
#define NW8 (512 * 1536 / 8)   // 98304 uint4 outputs for W
#define NTOT8 (NU8 + NW8)
#define PRE_ITERS 4
#define PRE_BLK 256
#define PRE_GRID ((NTOT8 + PRE_BLK * PRE_ITERS - 1) / (PRE_BLK * PRE_ITERS))

__device__ __half g_Uh[32768 * 512];
__device__ __half g_Wh[512 * 1536];

__device__ __forceinline__ uint32_t s2u(const void* p) {
    uint32_t a;
    asm("{ .reg .u64 t; cvta.to.shared.u64 t, %1; cvt.u32.u64 %0, t; }" : "=r"(a) : "l"(p));
    return a;
}
__device__ __forceinline__ void cp16(uint32_t dst, const void* src) {
    asm volatile("cp.async.cg.shared.global [%0], [%1], 16;" :: "r"(dst), "l"(src));
}
__device__ __forceinline__ void ldsm4(uint32_t addr, uint32_t* r) {
    asm volatile("ldmatrix.sync.aligned.m8n8.x4.shared.b16 {%0,%1,%2,%3}, [%4];"
                 : "=r"(r[0]), "=r"(r[1]), "=r"(r[2]), "=r"(r[3]) : "r"(addr));
}
__device__ __forceinline__ void mma16(float* d, const uint32_t* a, uint32_t b0, uint32_t b1) {
    asm volatile(
        "mma.sync.aligned.m16n8k16.row.col.f32.f16.f16.f32 "
        "{%0,%1,%2,%3}, {%4,%5,%6,%7}, {%8,%9}, {%0,%1,%2,%3};"
        : "+f"(d[0]), "+f"(d[1]), "+f"(d[2]), "+f"(d[3])
        : "r"(a[0]), "r"(a[1]), "r"(a[2]), "r"(a[3]), "r"(b0), "r"(b1));
}

#define MBAR_INIT(a, c) \
    asm volatile("mbarrier.init.shared.b64 [%0], %1;" :: "r"(a), "r"(c) : "memory")
#define MBAR_ARRIVE(a) \
    asm volatile("mbarrier.arrive.shared.b64 _, [%0];" :: "r"(a) : "memory")
#define CPASYNC_MBAR_ARRIVE(a) \
    asm volatile("cp.async.mbarrier.arrive.noinc.shared.b64 [%0];" :: "r"(a) : "memory")
#define MBAR_WAIT(a, ph) do {                                                 \
    asm volatile(                                                             \
        "{\n\t.reg .pred P1;\n\t"                                             \
        "WAIT_LOOP_%=:\n\t"                                                   \
        "mbarrier.try_wait.parity.acquire.cta.shared::cta.b64 P1, [%0], %1, 0x989680;\n\t" \
        "@P1 bra.uni WAIT_DONE_%=;\n\t"                                       \
        "bra.uni WAIT_LOOP_%=;\n\t"                                           \
        "WAIT_DONE_%=:\n\t}"                                                  \
        :: "r"(a), "r"(ph) : "memory");                                       \
} while (0)

// ---------------------------------------------------------------------------
// prepass: 4 independent 16B loads+stores per thread (MLP ~8 incl. float4 pair)
__global__ void __launch_bounds__(PRE_BLK) f2h_fused(const float* __restrict__ U,
                                                     const float* __restrict__ W) {
    const int base = blockIdx.x * (PRE_BLK * PRE_ITERS) + threadIdx.x;
    int idx[PRE_ITERS];
    float4 v0[PRE_ITERS], v1[PRE_ITERS];
    bool ok[PRE_ITERS];
    #pragma unroll
    for (int k = 0; k < PRE_ITERS; k++) {
        idx[k] = base + k * PRE_BLK;
        ok[k] = idx[k] < NTOT8;
        const float4* src = (idx[k] < NU8)
            ? ((const float4*)U + (size_t)idx[k] * 2)
            : ((const float4*)W + (size_t)(idx[k] - NU8) * 2);
        if (ok[k]) { v0[k] = src[0]; v1[k] = src[1]; }
    }
    #pragma unroll
    for (int k = 0; k < PRE_ITERS; k++) {
        if (!ok[k]) continue;
        __half2 h0 = __floats2half2_rn(v0[k].x, v0[k].y);
        __half2 h1 = __floats2half2_rn(v0[k].z, v0[k].w);
        __half2 h2 = __floats2half2_rn(v1[k].x, v1[k].y);
        __half2 h3 = __floats2half2_rn(v1[k].z, v1[k].w);
        uint4 pk;
        pk.x = *(uint32_t*)&h0; pk.y = *(uint32_t*)&h1;
        pk.z = *(uint32_t*)&h2; pk.w = *(uint32_t*)&h3;
        uint4* dst = (idx[k] < NU8) ? ((uint4*)g_Uh + idx[k])
                                    : ((uint4*)g_Wh + (idx[k] - NU8));
        *dst = pk;
    }
}

// ---------------------------------------------------------------------------
__global__ void __launch_bounds__(256, 2)
suc_mma_kernel(const float* __restrict__ lq,
               const float* __restrict__ bias, float* __restrict__ out)
{
    extern __shared__ __align__(16) char smem[];
    const uint32_t sb = s2u(smem);
    char* stage_base = smem + MBAR_BYTES;
    const int tid = threadIdx.x;
    const int lane = tid & 31;
    const int wid = tid >> 5;
    const int wm = wid & 3;
    const int wn = wid >> 2;
    const int n0 = blockIdx.x * BN;
    const int r0 = blockIdx.y * BM;
    const bool zb = (((r0 + BM) & 1023) == 0);

    if (tid == 0) {
        MBAR_INIT(sb + OFF_FULL(0), 256);
        MBAR_INIT(sb + OFF_FULL(1), 256);
        MBAR_INIT(sb + OFF_EMPTY(0), 256);
        MBAR_INIT(sb + OFF_EMPTY(1), 256);
    }
    if (zb && tid < 64) {
        int s = tid >> 5, w = tid & 31;
        ((uint32_t*)(stage_base + s * STAGE + 128 * ROWSTRIDE))[w] = 0u;
    }
    __syncthreads();   // one-time: mbarrier init + zeroing visible

    const uint32_t stg = sb + MBAR_BYTES;

    auto issue_load = [&](int c, int s) {
        const int kt = c * BK;
        const uint32_t stb = stg + s * STAGE;
        #pragma unroll 1
        for (int i = tid; i < TOT_CNT; i += 256) {
            if (i < A_CNT) {
                int r = i >> 3, cc = i & 7;
                if (!(zb && r == 128))
                    cp16(stb + r * ROWSTRIDE + cc * 16,
                         &g_Uh[(r0 + r) * 512 + kt + cc * 8]);
            } else {
                int b = i - A_CNT;
                int band = b >> 9, rem = b & 511, n = rem >> 3, cc = rem & 7;
                cp16(stb + A_BYTES + band * B_BAND_BYTES + n * ROWSTRIDE + cc * 16,
                     &g_Wh[(n0 + n) * 1536 + band * 512 + kt + cc * 8]);
            }
        }
        CPASYNC_MBAR_ARRIVE(sb + OFF_FULL(s));
    };

    uint32_t aoff[2];
    #pragma unroll
    for (int mt = 0; mt < 2; mt++)
        aoff[mt] = (wm * 32 + mt * 16 + (lane & 15)) * ROWSTRIDE + (lane >> 4) * 16;
    uint32_t boff[3][2];
    #pragma unroll
    for (int band = 0; band < 3; band++)
        #pragma unroll
        for (int p = 0; p < 2; p++)
            boff[band][p] = A_BYTES + band * B_BAND_BYTES
                + (wn * 32 + p * 16 + (lane & 7) + ((lane >> 4) & 1) * 8) * ROWSTRIDE
                + ((lane >> 3) & 1) * 16;

    float ae[2][4][4] = {};
    float ao[2][4][4] = {};

    issue_load(0, 0);
    issue_load(1, 1);

    #pragma unroll 1
    for (int c = 0; c < NCHUNK; ++c) {
        const int s = c & 1;
        const uint32_t ph = (c >> 1) & 1;
        MBAR_WAIT(sb + OFF_FULL(s), ph);

        const uint32_t stb = stg + s * STAGE;
        #pragma unroll
        for (int g = 0; g < 4; g++) {
            const uint32_t ko = g * 32;
            uint32_t a[2][4], as[2][4];
            #pragma unroll
            for (int mt = 0; mt < 2; mt++) {
                ldsm4(stb + aoff[mt] + ko, a[mt]);
                ldsm4(stb + aoff[mt] + ROWSTRIDE + ko, as[mt]);   // +1 row shift
            }
            uint32_t b1[2][4], b0[2][4], b2[2][4];
            ldsm4(stb + boff[1][0] + ko, b1[0]);
            ldsm4(stb + boff[1][1] + ko, b1[1]);
            ldsm4(stb + boff[0][0] + ko, b0[0]);
            ldsm4(stb + boff[0][1] + ko, b0[1]);
            ldsm4(stb + boff[2][0] + ko, b2[0]);
            ldsm4(stb + boff[2][1] + ko, b2[1]);
            #pragma unroll
            for (int mt = 0; mt < 2; mt++)
                #pragma unroll
                for (int nt = 0; nt < 4; nt++) {
                    const int hp = nt >> 1, hq = (nt & 1) * 2;
                    mma16(ae[mt][nt], a[mt], b1[hp][hq], b1[hp][hq + 1]);
                    mma16(ao[mt][nt], a[mt], b0[hp][hq], b0[hp][hq + 1]);
                }
            #pragma unroll
            for (int mt = 0; mt < 2; mt++)
                #pragma unroll
                for (int nt = 0; nt < 4; nt++) {
                    const int hp = nt >> 1, hq = (nt & 1) * 2;
                    mma16(ao[mt][nt], as[mt], b2[hp][hq], b2[hp][hq + 1]);
                }
        }
        MBAR_ARRIVE(sb + OFF_EMPTY(s));
        if (c + 2 < NCHUNK) {
            MBAR_WAIT(sb + OFF_EMPTY(s), ph);
            issue_load(c + 2, s);
        }
    }

    // ---- fused epilogue: bias + relu + residual + res_connect ----
    const int l4 = lane >> 2;
    const int l2 = (lane & 3) * 2;
    #pragma unroll
    for (int mt = 0; mt < 2; mt++) {
        #pragma unroll
        for (int h = 0; h < 2; h++) {
            const int rg = r0 + wm * 32 + mt * 16 + h * 8 + l4;
            const int j = rg & 1023;
            const int bh = rg >> 10;
            const bool v1 = (j != 1023);
            const int ie_base = (bh * 2048 + 2 * j) * 512;
            #pragma unroll
            for (int nt = 0; nt < 4; nt++) {
                const int dof = n0 + wn * 32 + nt * 8 + l2;
                const float2 u0 = __half22float2(*(const __half2*)&g_Uh[rg * 512 + dof]);
                float2 u1 = make_float2(0.f, 0.f);
                if (v1) u1 = __half22float2(*(const __half2*)&g_Uh[(rg + 1) * 512 + dof]);
                const float2 bv = *(const float2*)&bias[dof];
                const int ie = ie_base + dof;
                const int io = ie + 512;
                const float2 lqe = *(const float2*)&lq[ie];
                const float2 lqo = *(const float2*)&lq[io];
                const float e0 = ae[mt][nt][h * 2 + 0], e1 = ae[mt][nt][h * 2 + 1];
                const float o0 = ao[mt][nt][h * 2 + 0], o1 = ao[mt][nt][h * 2 + 1];
                float2 re, ro;
                re.x = lqe.x + fmaxf(e0 + bv.x, 0.f) + u0.x * (1.f / 3.f);
                re.y = lqe.y + fmaxf(e1 + bv.y, 0.f) + u0.y * (1.f / 3.f);
                ro.x = lqo.x + fmaxf(o0 + bv.x, 0.f) + (u0.x + u1.x) * (1.f / 3.f);
                ro.y = lqo.y + fmaxf(o1 + bv.y, 0.f) + (u0.y + u1.y) * (1.f / 3.f);
                *(float2*)&out[ie] = re;
                *(float2*)&out[io] = ro;
            }
        }
    }
}

// ============================================================================
extern "C" void kernel_launch(void* const* d_in, const int* in_sizes, int n_in,
                              void* d_out, int out_size)
{
    const float* lq   = (const float*)d_in[0];
    const float* U    = (const float*)d_in[1];
    const float* W    = (const float*)d_in[2];
    const float* bias = (const float*)d_in[3];

    f2h_fused<<<PRE_GRID, PRE_BLK>>>(U, W);

    cudaFuncSetAttribute(suc_mma_kernel, cudaFuncAttributeMaxDynamicSharedMemorySize,
                         SMEM_BYTES);
    dim3 grid(512 / BN, 32768 / BM);  // (8, 256)
    suc_mma_kernel<<<grid, 256, SMEM_BYTES>>>(lq, bias, (float*)d_out);
}